// round 3
// baseline (speedup 1.0000x reference)
#include <cuda_runtime.h>

#define DIMX   1024
#define NH     16
#define HDIM   64
#define LAT    128
#define QRANK  256
#define BATCH  4
#define SEQ    2048
#define MTOT   (BATCH*SEQ)   // 8192

// ---------------- scratch (device globals: no allocation allowed) -----------
__device__ float g_kvl[(size_t)MTOT * LAT];          //  4 MB
__device__ float g_kv [(size_t)MTOT * 2 * DIMX];     // 64 MB (K | V concat)
__device__ float g_qc [(size_t)MTOT * QRANK];        //  8 MB
__device__ float g_q  [(size_t)MTOT * DIMX];         // 32 MB
__device__ float g_ctx[(size_t)MTOT * DIMX];         // 32 MB

// ---------------- generic tiled fp32 GEMM with fused bias -------------------
// C[M,N] = A[M,K] @ B[K,N] + bias[N]; all row-major. K%BK==0, M%BM==0, N%BN==0.
template<int BM, int BN, int BK, int TM, int TN>
__global__ __launch_bounds__((BM/TM)*(BN/TN))
void gemm_bias_kernel(const float* __restrict__ A, const float* __restrict__ B,
                      const float* __restrict__ bias, float* __restrict__ C,
                      int M, int N, int K)
{
    constexpr int NT = (BM/TM)*(BN/TN);
    __shared__ float As[BK][BM];
    __shared__ float Bs[BK][BN];

    const int tid  = threadIdx.x;
    const int tcol = tid % (BN/TN);
    const int trow = tid / (BN/TN);
    const int m0   = blockIdx.y * BM;
    const int n0   = blockIdx.x * BN;

    float acc[TM][TN];
#pragma unroll
    for (int i = 0; i < TM; i++)
#pragma unroll
        for (int j = 0; j < TN; j++) acc[i][j] = 0.f;

    for (int k0 = 0; k0 < K; k0 += BK) {
        // load A tile (BM x BK), transpose into As[k][m]
        for (int i = tid*4; i < BM*BK; i += NT*4) {
            int r = i / BK, c = i % BK;
            float4 v = *(const float4*)(A + (size_t)(m0 + r)*K + k0 + c);
            As[c+0][r] = v.x; As[c+1][r] = v.y; As[c+2][r] = v.z; As[c+3][r] = v.w;
        }
        // load B tile (BK x BN)
        for (int i = tid*4; i < BK*BN; i += NT*4) {
            int r = i / BN, c = i % BN;
            *(float4*)&Bs[r][c] = *(const float4*)(B + (size_t)(k0 + r)*N + n0 + c);
        }
        __syncthreads();
#pragma unroll
        for (int kk = 0; kk < BK; kk++) {
            float rm[TM], rn[TN];
#pragma unroll
            for (int i = 0; i < TM; i++) rm[i] = As[kk][trow*TM + i];
#pragma unroll
            for (int j = 0; j < TN; j++) rn[j] = Bs[kk][tcol*TN + j];
#pragma unroll
            for (int i = 0; i < TM; i++)
#pragma unroll
                for (int j = 0; j < TN; j++) acc[i][j] += rm[i]*rn[j];
        }
        __syncthreads();
    }
#pragma unroll
    for (int i = 0; i < TM; i++) {
        int row = m0 + trow*TM + i;
#pragma unroll
        for (int j4 = 0; j4 < TN; j4 += 4) {
            int col = n0 + tcol*TN + j4;
            float4 b4 = *(const float4*)(bias + col);
            float4 o;
            o.x = acc[i][j4+0] + b4.x;
            o.y = acc[i][j4+1] + b4.y;
            o.z = acc[i][j4+2] + b4.z;
            o.w = acc[i][j4+3] + b4.w;
            *(float4*)(C + (size_t)row*N + col) = o;
        }
    }
}

// ---------------- flash attention (causal, fp32, hd=64) ---------------------
// grid: (SEQ/64, NH, BATCH), 256 threads. Q pre-scaled by 1/8 at load.
// K tile stored with XOR chunk swizzle for conflict-free column-slab LDS.128.
// K buffer is reused for the P tile (same swizzle, half-warp produce/consume).
__global__ __launch_bounds__(256)
void flash_attn_kernel(const float* __restrict__ Qm, const float* __restrict__ KVm,
                       float* __restrict__ Om)
{
    __shared__ float Qs[64*64];
    __shared__ float Ks[64*64];   // doubles as P tile
    __shared__ float Vs[64*64];

    const int tid = threadIdx.x;
    const int tx  = tid & 15;
    const int ty  = tid >> 4;
    const int r0  = ty << 2;           // 4 query rows
    const int c0  = tx << 2;           // 4 key cols / out dims
    const int q0  = blockIdx.x << 6;
    const int h   = blockIdx.y;
    const int b   = blockIdx.z;

    const float* Qg = Qm  + ((size_t)(b*SEQ + q0))*DIMX + h*HDIM;
    const float* Kg = KVm + ((size_t)(b*SEQ))*(2*DIMX)  + h*HDIM;
    const float* Vg = Kg + DIMX;

    // load Q tile, pre-scaled by 1/sqrt(64)
    for (int i = tid; i < 64*16; i += 256) {
        int rr = i >> 4, c4 = (i & 15) << 2;
        float4 v = *(const float4*)(Qg + (size_t)rr*DIMX + c4);
        float* d = Qs + rr*64 + c4;
        d[0] = v.x*0.125f; d[1] = v.y*0.125f; d[2] = v.z*0.125f; d[3] = v.w*0.125f;
    }

    float m_i[4], l_i[4], acc[4][4];
#pragma unroll
    for (int i = 0; i < 4; i++) {
        m_i[i] = -1e30f; l_i[i] = 0.f;
#pragma unroll
        for (int j = 0; j < 4; j++) acc[i][j] = 0.f;
    }
    __syncthreads();

    const int nt = (q0 >> 6) + 1;     // causal: only tiles with k0 <= q0
    for (int kt = 0; kt < nt; kt++) {
        const int k0 = kt << 6;
        if (kt) __syncthreads();      // protect Ks(=P)/Vs from previous iter
        // load K (swizzled) and V tiles
        for (int i = tid; i < 64*16; i += 256) {
            int rr = i >> 4, ch = i & 15;
            float4 kv4 = *(const float4*)(Kg + (size_t)(k0 + rr)*(2*DIMX) + (ch<<2));
            int pch = ch ^ ((rr >> 2) & 7);
            *(float4*)(Ks + rr*64 + (pch<<2)) = kv4;
            float4 vv4 = *(const float4*)(Vg + (size_t)(k0 + rr)*(2*DIMX) + (ch<<2));
            *(float4*)(Vs + rr*64 + (ch<<2)) = vv4;
        }
        __syncthreads();

        // S = Q K^T  (4x4 per thread)
        float s[4][4];
#pragma unroll
        for (int i = 0; i < 4; i++)
#pragma unroll
            for (int j = 0; j < 4; j++) s[i][j] = 0.f;

#pragma unroll 4
        for (int d4 = 0; d4 < 16; d4++) {
            float4 rq[4], rk[4];
#pragma unroll
            for (int i = 0; i < 4; i++)
                rq[i] = *(const float4*)(Qs + (r0 + i)*64 + (d4<<2));
#pragma unroll
            for (int j = 0; j < 4; j++) {
                int row = c0 + j;                       // row>>2 == tx
                int pch = d4 ^ (tx & 7);
                rk[j] = *(const float4*)(Ks + row*64 + (pch<<2));
            }
#pragma unroll
            for (int i = 0; i < 4; i++)
#pragma unroll
                for (int j = 0; j < 4; j++)
                    s[i][j] += rq[i].x*rk[j].x + rq[i].y*rk[j].y
                             + rq[i].z*rk[j].z + rq[i].w*rk[j].w;
        }

        // causal mask (only the diagonal tile needs it)
        if (k0 == q0) {
#pragma unroll
            for (int i = 0; i < 4; i++)
#pragma unroll
                for (int j = 0; j < 4; j++)
                    if (c0 + j > r0 + i) s[i][j] = -1e30f;
        }

        // online softmax (row state replicated across the 16 tx lanes)
#pragma unroll
        for (int i = 0; i < 4; i++) {
            float mx = fmaxf(fmaxf(s[i][0], s[i][1]), fmaxf(s[i][2], s[i][3]));
#pragma unroll
            for (int off = 8; off > 0; off >>= 1)
                mx = fmaxf(mx, __shfl_xor_sync(0xffffffffu, mx, off));
            float mn = fmaxf(m_i[i], mx);
            float al = __expf(m_i[i] - mn);
            m_i[i] = mn;
            float rs = 0.f;
#pragma unroll
            for (int j = 0; j < 4; j++) { s[i][j] = __expf(s[i][j] - mn); rs += s[i][j]; }
#pragma unroll
            for (int off = 8; off > 0; off >>= 1)
                rs += __shfl_xor_sync(0xffffffffu, rs, off);
            l_i[i] = l_i[i]*al + rs;
#pragma unroll
            for (int j = 0; j < 4; j++) acc[i][j] *= al;
        }

        __syncthreads();               // everyone done reading Ks
        // write P into Ks (swizzled): logical chunk for this thread is tx
#pragma unroll
        for (int i = 0; i < 4; i++) {
            int row = r0 + i;                          // row>>2 == ty
            int pch = tx ^ (ty & 7);
            *(float4*)(Ks + row*64 + (pch<<2)) =
                make_float4(s[i][0], s[i][1], s[i][2], s[i][3]);
        }
        __syncwarp();                  // P rows produced/consumed by same half-warp

        // O += P @ V
#pragma unroll 4
        for (int k4 = 0; k4 < 16; k4++) {
            float rpa[4][4];
#pragma unroll
            for (int i = 0; i < 4; i++) {
                int row = r0 + i;                      // row>>2 == ty
                float4 rp = *(const float4*)(Ks + row*64 + ((k4 ^ (ty & 7))<<2));
                rpa[i][0] = rp.x; rpa[i][1] = rp.y; rpa[i][2] = rp.z; rpa[i][3] = rp.w;
            }
#pragma unroll
            for (int kk = 0; kk < 4; kk++) {
                int k = (k4<<2) + kk;
                float4 rv = *(const float4*)(Vs + k*64 + c0);
#pragma unroll
                for (int i = 0; i < 4; i++) {
                    float p = rpa[i][kk];
                    acc[i][0] += p*rv.x; acc[i][1] += p*rv.y;
                    acc[i][2] += p*rv.z; acc[i][3] += p*rv.w;
                }
            }
        }
    }

    // epilogue: normalize and write ctx[b, s, h*64 + d]
    float* Og = Om + ((size_t)(b*SEQ + q0))*DIMX + h*HDIM;
#pragma unroll
    for (int i = 0; i < 4; i++) {
        float inv = 1.0f / l_i[i];
        *(float4*)(Og + (size_t)(r0 + i)*DIMX + c0) =
            make_float4(acc[i][0]*inv, acc[i][1]*inv, acc[i][2]*inv, acc[i][3]*inv);
    }
}

// ---------------- launch --------------------------------------------------
extern "C" void kernel_launch(void* const* d_in, const int* in_sizes, int n_in,
                              void* d_out, int out_size)
{
    (void)in_sizes; (void)n_in; (void)out_size;
    const float* x     = (const float*)d_in[0];
    // d_in[1] = mask (causal tril by construction; attention exploits it directly)
    const float* w_kvc = (const float*)d_in[2];
    const float* b_kvc = (const float*)d_in[3];
    const float* w_kvu = (const float*)d_in[4];
    const float* b_kvu = (const float*)d_in[5];
    const float* w_qc  = (const float*)d_in[6];
    const float* b_qc  = (const float*)d_in[7];
    const float* w_qu  = (const float*)d_in[8];
    const float* b_qu  = (const float*)d_in[9];
    const float* w_o   = (const float*)d_in[10];
    const float* b_o   = (const float*)d_in[11];
    float* out = (float*)d_out;

    float *kvl, *kv, *qc, *q, *ctx;
    cudaGetSymbolAddress((void**)&kvl, g_kvl);
    cudaGetSymbolAddress((void**)&kv,  g_kv);
    cudaGetSymbolAddress((void**)&qc,  g_qc);
    cudaGetSymbolAddress((void**)&q,   g_q);
    cudaGetSymbolAddress((void**)&ctx, g_ctx);

    // kv_latent = x @ w_kvc + b_kvc          [8192,128]
    gemm_bias_kernel<64,128,8,4,8><<<dim3(LAT/128, MTOT/64), 256>>>(
        x, w_kvc, b_kvc, kvl, MTOT, LAT, DIMX);
    // kv_up = kv_latent @ w_kvu + b_kvu      [8192,2048] = [K | V]
    gemm_bias_kernel<128,128,8,8,8><<<dim3(2*DIMX/128, MTOT/128), 256>>>(
        kvl, w_kvu, b_kvu, kv, MTOT, 2*DIMX, LAT);
    // qc = x @ w_qc + b_qc                   [8192,256]
    gemm_bias_kernel<64,128,8,4,8><<<dim3(QRANK/128, MTOT/64), 256>>>(
        x, w_qc, b_qc, qc, MTOT, QRANK, DIMX);
    // Q = qc @ w_qu + b_qu                   [8192,1024]
    gemm_bias_kernel<128,128,8,8,8><<<dim3(DIMX/128, MTOT/128), 256>>>(
        qc, w_qu, b_qu, q, MTOT, DIMX, QRANK);
    // ctx = causal softmax attention
    flash_attn_kernel<<<dim3(SEQ/64, NH, BATCH), 256>>>(q, kv, ctx);
    // out = ctx @ w_o + b_o                  [8192,1024]
    gemm_bias_kernel<128,128,8,8,8><<<dim3(DIMX/128, MTOT/128), 256>>>(
        ctx, w_o, b_o, out, MTOT, DIMX, DIMX);
}

// round 6
// speedup vs baseline: 3.0293x; 3.0293x over previous
#include <cuda_runtime.h>

#define DIMX   1024
#define NH     16
#define HDIM   64
#define LAT    128
#define QRANK  256
#define BATCH  4
#define SEQ    2048
#define MTOT   (BATCH*SEQ)   // 8192

// ---------------- scratch (device globals: no allocation allowed) -----------
__device__ float g_kvl[(size_t)MTOT * LAT];
__device__ float g_kv [(size_t)MTOT * 2 * DIMX];     // [K | V] per row
__device__ float g_qcb[(size_t)MTOT * QRANK];
__device__ float g_q  [(size_t)MTOT * DIMX];
__device__ float g_ctx[(size_t)MTOT * DIMX];
__device__ float g_vt [(size_t)BATCH * DIMX * SEQ];  // V^T per batch: [b][d][s]
__device__ float g_wT [1966080];                     // transposed weights

// offsets into g_wT (floats)
#define WT_KVC 0          // [128][1024]
#define WT_KVU 131072     // [2048][128]
#define WT_QC  393216     // [256][1024]
#define WT_QU  655360     // [1024][256]
#define WT_O   917504     // [1024][1024]

// ---------------- mma/ldmatrix helpers --------------------------------------
__device__ __forceinline__ unsigned f2tf(float x){
    unsigned r; asm("cvt.rna.tf32.f32 %0, %1;" : "=r"(r) : "f"(x)); return r;
}
__device__ __forceinline__ void ldsm4(unsigned* r, unsigned a){
    asm volatile("ldmatrix.sync.aligned.m8n8.x4.shared.b16 {%0,%1,%2,%3}, [%4];"
        : "=r"(r[0]), "=r"(r[1]), "=r"(r[2]), "=r"(r[3]) : "r"(a));
}
__device__ __forceinline__ void mma8(float* c, const unsigned* a, const unsigned* b){
    asm volatile("mma.sync.aligned.m16n8k8.row.col.f32.tf32.tf32.f32 "
        "{%0,%1,%2,%3}, {%4,%5,%6,%7}, {%8,%9}, {%0,%1,%2,%3};"
        : "+f"(c[0]), "+f"(c[1]), "+f"(c[2]), "+f"(c[3])
        : "r"(a[0]), "r"(a[1]), "r"(a[2]), "r"(a[3]), "r"(b[0]), "r"(b[1]));
}

// swizzled float-index: tile row stride 32 floats (8 chunks of 16B)
#define SWZ32(r,c) (((r)<<5) + ((((c) ^ ((r)&7)) & 7) << 2))
// tile row stride 64 floats (16 chunks): swizzle low 3 bits of chunk
#define SWZ64(r,c) (((r)<<6) + (((((c)&8) | (((c) ^ (r)) & 7))) << 2))

// ---------------- batched transpose: out[b][c][r] = in[b][r][c] -------------
__global__ void transpose_kernel(const float* __restrict__ in, float* __restrict__ out,
                                 int R, int C, int ics, size_t ibs, size_t obs)
{
    __shared__ float t[32][33];
    const float* ib = in  + blockIdx.z * ibs;
    float*       ob = out + blockIdx.z * obs;
    int r0 = blockIdx.y * 32, c0 = blockIdx.x * 32;
    int tx = threadIdx.x, ty = threadIdx.y;
#pragma unroll
    for (int i = 0; i < 32; i += 8)
        t[ty + i][tx] = ib[(size_t)(r0 + ty + i) * ics + c0 + tx];
    __syncthreads();
#pragma unroll
    for (int i = 0; i < 32; i += 8)
        ob[(size_t)(c0 + ty + i) * R + r0 + tx] = t[tx][ty + i];
}

// ---------------- tf32 mma GEMM: C[M,N] = A[M,K] @ Bt[N,K]^T + bias ---------
// BM=BN=128, BK=32, 256 threads, warp grid 2x4, warp tile 64x32.
__global__ __launch_bounds__(256)
void gemm_mma(const float* __restrict__ A, const float* __restrict__ Bt,
              const float* __restrict__ bias, float* __restrict__ C,
              int M, int N, int K)
{
    __shared__ float As[128*32];
    __shared__ float Bs[128*32];
    const int tid  = threadIdx.x;
    const int lane = tid & 31, warp = tid >> 5;
    const int wm = warp >> 2, wn = warp & 3;
    const int m0 = blockIdx.y * 128, n0 = blockIdx.x * 128;

    const unsigned sA = (unsigned)__cvta_generic_to_shared(As);
    const unsigned sB = (unsigned)__cvta_generic_to_shared(Bs);

    float cacc[4][4][4];
#pragma unroll
    for (int i = 0; i < 4; i++)
#pragma unroll
        for (int j = 0; j < 4; j++)
#pragma unroll
            for (int v = 0; v < 4; v++) cacc[i][j][v] = 0.f;

    const int lrow = tid >> 3;        // 0..31
    const int lc4  = tid & 7;         // k-chunk 0..7
    const int g    = lane >> 2, t4 = lane & 3;
    const int ar   = lane & 15;       // ldmatrix A row offset
    const int asel = lane >> 4;       // +0/+1 k-chunk

    for (int k0 = 0; k0 < K; k0 += 32) {
#pragma unroll
        for (int i = 0; i < 4; i++) {
            int r = lrow + 32*i;
            float4 va = *(const float4*)(A  + (size_t)(m0 + r)*K + k0 + 4*lc4);
            float4 vb = *(const float4*)(Bt + (size_t)(n0 + r)*K + k0 + 4*lc4);
            uint4 ua = make_uint4(f2tf(va.x), f2tf(va.y), f2tf(va.z), f2tf(va.w));
            uint4 ub = make_uint4(f2tf(vb.x), f2tf(vb.y), f2tf(vb.z), f2tf(vb.w));
            *(uint4*)(As + SWZ32(r, lc4)) = ua;
            *(uint4*)(Bs + SWZ32(r, lc4)) = ub;
        }
        __syncthreads();
#pragma unroll
        for (int kk = 0; kk < 4; kk++) {
            unsigned af[4][4];
#pragma unroll
            for (int mi = 0; mi < 4; mi++)
                ldsm4(af[mi], sA + 4*SWZ32(64*wm + 16*mi + ar, 2*kk + asel));
            unsigned bt[2][4];
#pragma unroll
            for (int p = 0; p < 2; p++) {
                int brow = 32*wn + 8*(2*p + (lane >> 4)) + (lane & 7);
                int bch  = 2*kk + ((lane >> 3) & 1);
                ldsm4(bt[p], sB + 4*SWZ32(brow, bch));
            }
#pragma unroll
            for (int mi = 0; mi < 4; mi++)
#pragma unroll
                for (int nj = 0; nj < 4; nj++)
                    mma8(cacc[mi][nj], af[mi], &bt[nj >> 1][2*(nj & 1)]);
        }
        __syncthreads();
    }
    // epilogue: += bias, write float2
#pragma unroll
    for (int mi = 0; mi < 4; mi++) {
        int row = m0 + 64*wm + 16*mi + g;
#pragma unroll
        for (int nj = 0; nj < 4; nj++) {
            int col = n0 + 32*wn + 8*nj + 2*t4;
            float2 b2 = *(const float2*)(bias + col);
            float2 o0 = make_float2(cacc[mi][nj][0] + b2.x, cacc[mi][nj][1] + b2.y);
            float2 o1 = make_float2(cacc[mi][nj][2] + b2.x, cacc[mi][nj][3] + b2.y);
            *(float2*)(C + (size_t)row*N + col)       = o0;
            *(float2*)(C + (size_t)(row + 8)*N + col) = o1;
        }
    }
}

// ---------------- tf32 mma flash attention (causal, hd=64) ------------------
// 128 threads = 4 warps; warp w owns q rows 16w..16w+15. BM=BN=64.
// Buffers: sQP (Q then P), sK [key][d], sV [d][key] (V pre-transposed in gmem).
__global__ __launch_bounds__(128)
void flash_mma(const float* __restrict__ Qm, const float* __restrict__ KVm,
               const float* __restrict__ Vt, float* __restrict__ Om)
{
    __shared__ float sQP[64*64];
    __shared__ float sK [64*64];
    __shared__ float sV [64*64];

    const int tid  = threadIdx.x;
    const int lane = tid & 31, w = tid >> 5;
    const int g = lane >> 2, t4 = lane & 3;
    const int qt = (gridDim.x - 1) - blockIdx.x;   // largest-work blocks first
    const int q0 = qt << 6;
    const int h  = blockIdx.y;
    const int b  = blockIdx.z;

    const unsigned sQPa = (unsigned)__cvta_generic_to_shared(sQP);
    const unsigned sKa  = (unsigned)__cvta_generic_to_shared(sK);
    const unsigned sVa  = (unsigned)__cvta_generic_to_shared(sV);

    const float* Qg = Qm  + ((size_t)(b*SEQ + q0))*DIMX + h*HDIM;
    const float* Kg = KVm + ((size_t)(b*SEQ))*(2*DIMX)  + h*HDIM;
    const float* Vg = Vt  + ((size_t)(b*DIMX + h*HDIM))*SEQ;

    // load Q tile (scaled, tf32-rounded)
#pragma unroll
    for (int i = 0; i < 8; i++) {
        int lin = tid + (i << 7);
        int r = lin >> 4, c4 = lin & 15;
        float4 v = *(const float4*)(Qg + (size_t)r*DIMX + (c4 << 2));
        uint4 u = make_uint4(f2tf(v.x*0.125f), f2tf(v.y*0.125f),
                             f2tf(v.z*0.125f), f2tf(v.w*0.125f));
        *(uint4*)(sQP + SWZ64(r, c4)) = u;
    }
    __syncthreads();

    // Q fragments -> registers (16 rows x 64 d per warp)
    unsigned qf[8][4];
#pragma unroll
    for (int kk = 0; kk < 8; kk++)
        ldsm4(qf[kk], sQPa + 4*SWZ64(16*w + (lane & 15), 2*kk + (lane >> 4)));

    float m_i[2] = {-1e30f, -1e30f}, l_i[2] = {0.f, 0.f};
    float oacc[8][4];
#pragma unroll
    for (int j = 0; j < 8; j++)
#pragma unroll
        for (int v = 0; v < 4; v++) oacc[j][v] = 0.f;

    const int row0 = q0 + 16*w + g;
    const int nt = qt + 1;
    for (int kt = 0; kt < nt; kt++) {
        const int k0 = kt << 6;
        __syncthreads();   // K/V/QP(P) free to overwrite; covers Q-frag loads on iter 0
        // load K [key][d] and V [d][key] tiles (tf32-rounded)
#pragma unroll
        for (int i = 0; i < 8; i++) {
            int lin = tid + (i << 7);
            int r = lin >> 4, c4 = lin & 15;
            float4 kv = *(const float4*)(Kg + (size_t)(k0 + r)*(2*DIMX) + (c4 << 2));
            *(uint4*)(sK + SWZ64(r, c4)) =
                make_uint4(f2tf(kv.x), f2tf(kv.y), f2tf(kv.z), f2tf(kv.w));
            float4 vv = *(const float4*)(Vg + (size_t)r*SEQ + k0 + (c4 << 2));
            *(uint4*)(sV + SWZ64(r, c4)) =
                make_uint4(f2tf(vv.x), f2tf(vv.y), f2tf(vv.z), f2tf(vv.w));
        }
        __syncthreads();

        // S = Q K^T : warp tile 16 x 64 (8 n-tiles)
        float sacc[8][4];
#pragma unroll
        for (int j = 0; j < 8; j++)
#pragma unroll
            for (int v = 0; v < 4; v++) sacc[j][v] = 0.f;
#pragma unroll
        for (int kk = 0; kk < 8; kk++) {
            unsigned bt[4][4];
#pragma unroll
            for (int p = 0; p < 4; p++) {
                int brow = 8*(2*p + (lane >> 4)) + (lane & 7);
                int bch  = 2*kk + ((lane >> 3) & 1);
                ldsm4(bt[p], sKa + 4*SWZ64(brow, bch));
            }
#pragma unroll
            for (int j = 0; j < 8; j++)
                mma8(sacc[j], qf[kk], &bt[j >> 1][2*(j & 1)]);
        }

        // causal mask (diagonal tile only)
        if (kt == qt) {
#pragma unroll
            for (int j = 0; j < 8; j++) {
                int c = k0 + 8*j + 2*t4;
                if (c     > row0)     sacc[j][0] = -1e30f;
                if (c + 1 > row0)     sacc[j][1] = -1e30f;
                if (c     > row0 + 8) sacc[j][2] = -1e30f;
                if (c + 1 > row0 + 8) sacc[j][3] = -1e30f;
            }
        }

        // online softmax per row-half (rows g, g+8), reduce over 4 lanes
#pragma unroll
        for (int hf = 0; hf < 2; hf++) {
            float mx = -1e30f;
#pragma unroll
            for (int j = 0; j < 8; j++)
                mx = fmaxf(mx, fmaxf(sacc[j][2*hf], sacc[j][2*hf + 1]));
            mx = fmaxf(mx, __shfl_xor_sync(0xffffffffu, mx, 1));
            mx = fmaxf(mx, __shfl_xor_sync(0xffffffffu, mx, 2));
            float mn = fmaxf(m_i[hf], mx);
            float al = __expf(m_i[hf] - mn);
            m_i[hf] = mn;
            float rs = 0.f;
#pragma unroll
            for (int j = 0; j < 8; j++) {
                sacc[j][2*hf]     = __expf(sacc[j][2*hf]     - mn);
                sacc[j][2*hf + 1] = __expf(sacc[j][2*hf + 1] - mn);
                rs += sacc[j][2*hf] + sacc[j][2*hf + 1];
            }
            rs += __shfl_xor_sync(0xffffffffu, rs, 1);
            rs += __shfl_xor_sync(0xffffffffu, rs, 2);
            l_i[hf] = l_i[hf]*al + rs;
#pragma unroll
            for (int j = 0; j < 8; j++) {
                oacc[j][2*hf]     *= al;
                oacc[j][2*hf + 1] *= al;
            }
        }

        // write P (tf32) into sQP rows 16w..16w+15
#pragma unroll
        for (int j = 0; j < 8; j++) {
            int col = 8*j + 2*t4;
            int ch = col >> 2, wi = col & 3;
            uint2 p0 = make_uint2(f2tf(sacc[j][0]), f2tf(sacc[j][1]));
            uint2 p1 = make_uint2(f2tf(sacc[j][2]), f2tf(sacc[j][3]));
            *(uint2*)(sQP + SWZ64(16*w + g,     ch) + wi) = p0;
            *(uint2*)(sQP + SWZ64(16*w + g + 8, ch) + wi) = p1;
        }
        __syncwarp();

        // O += P @ V : k = keys (8 steps), n = d (8 tiles)
#pragma unroll
        for (int kk = 0; kk < 8; kk++) {
            unsigned pf[4];
            ldsm4(pf, sQPa + 4*SWZ64(16*w + (lane & 15), 2*kk + (lane >> 4)));
            unsigned bt[4][4];
#pragma unroll
            for (int p = 0; p < 4; p++) {
                int brow = 8*(2*p + (lane >> 4)) + (lane & 7);
                int bch  = 2*kk + ((lane >> 3) & 1);
                ldsm4(bt[p], sVa + 4*SWZ64(brow, bch));
            }
#pragma unroll
            for (int j = 0; j < 8; j++)
                mma8(oacc[j], pf, &bt[j >> 1][2*(j & 1)]);
        }
    }

    // epilogue: normalize, write ctx[b, q0+row][h*64 + d]
    float inv0 = 1.0f / l_i[0], inv1 = 1.0f / l_i[1];
    float* Og = Om + ((size_t)(b*SEQ + q0 + 16*w + g))*DIMX + h*HDIM;
#pragma unroll
    for (int j = 0; j < 8; j++) {
        int col = 8*j + 2*t4;
        *(float2*)(Og + col)           = make_float2(oacc[j][0]*inv0, oacc[j][1]*inv0);
        *(float2*)(Og + 8*DIMX + col)  = make_float2(oacc[j][2]*inv1, oacc[j][3]*inv1);
    }
}

// ---------------- launch ----------------------------------------------------
extern "C" void kernel_launch(void* const* d_in, const int* in_sizes, int n_in,
                              void* d_out, int out_size)
{
    (void)in_sizes; (void)n_in; (void)out_size;
    const float* x     = (const float*)d_in[0];
    // d_in[1] = mask (causal by construction; handled analytically)
    const float* w_kvc = (const float*)d_in[2];
    const float* b_kvc = (const float*)d_in[3];
    const float* w_kvu = (const float*)d_in[4];
    const float* b_kvu = (const float*)d_in[5];
    const float* w_qc  = (const float*)d_in[6];
    const float* b_qc  = (const float*)d_in[7];
    const float* w_qu  = (const float*)d_in[8];
    const float* b_qu  = (const float*)d_in[9];
    const float* w_o   = (const float*)d_in[10];
    const float* b_o   = (const float*)d_in[11];
    float* out = (float*)d_out;

    float *kvl, *kv, *qcb, *q, *ctx, *vt, *wT;
    cudaGetSymbolAddress((void**)&kvl, g_kvl);
    cudaGetSymbolAddress((void**)&kv,  g_kv);
    cudaGetSymbolAddress((void**)&qcb, g_qcb);
    cudaGetSymbolAddress((void**)&q,   g_q);
    cudaGetSymbolAddress((void**)&ctx, g_ctx);
    cudaGetSymbolAddress((void**)&vt,  g_vt);
    cudaGetSymbolAddress((void**)&wT,  g_wT);

    dim3 tb(32, 8);
    // transpose weights -> [N][K]
    transpose_kernel<<<dim3(128/32, 1024/32), tb>>>(w_kvc, wT + WT_KVC, 1024, 128,  128,  0, 0);
    transpose_kernel<<<dim3(2048/32, 128/32), tb>>>(w_kvu, wT + WT_KVU, 128,  2048, 2048, 0, 0);
    transpose_kernel<<<dim3(256/32, 1024/32), tb>>>(w_qc,  wT + WT_QC,  1024, 256,  256,  0, 0);
    transpose_kernel<<<dim3(1024/32, 256/32), tb>>>(w_qu,  wT + WT_QU,  256,  1024, 1024, 0, 0);
    transpose_kernel<<<dim3(1024/32, 1024/32), tb>>>(w_o,  wT + WT_O,   1024, 1024, 1024, 0, 0);

    // kv_latent = x @ w_kvc + b_kvc          [8192,128]
    gemm_mma<<<dim3(1, 64), 256>>>(x, wT + WT_KVC, b_kvc, kvl, MTOT, LAT, DIMX);
    // kv_up = kv_latent @ w_kvu + b_kvu      [8192,2048]
    gemm_mma<<<dim3(16, 64), 256>>>(kvl, wT + WT_KVU, b_kvu, kv, MTOT, 2*DIMX, LAT);
    // V^T per batch: vt[b][d][s]
    transpose_kernel<<<dim3(1024/32, 2048/32, BATCH), tb>>>(
        kv + DIMX, vt, SEQ, DIMX, 2*DIMX, (size_t)SEQ*2*DIMX, (size_t)DIMX*SEQ);
    // qc = x @ w_qc + b_qc                   [8192,256]
    gemm_mma<<<dim3(2, 64), 256>>>(x, wT + WT_QC, b_qc, qcb, MTOT, QRANK, DIMX);
    // Q = qc @ w_qu + b_qu                   [8192,1024]
    gemm_mma<<<dim3(8, 64), 256>>>(qcb, wT + WT_QU, b_qu, q, MTOT, DIMX, QRANK);
    // attention
    flash_mma<<<dim3(SEQ/64, NH, BATCH), 128>>>(q, kv, vt, ctx);
    // out = ctx @ w_o + b_o                  [8192,1024]
    gemm_mma<<<dim3(8, 64), 256>>>(ctx, wT + WT_O, b_o, out, MTOT, DIMX, DIMX);
}

// round 8
// speedup vs baseline: 3.7611x; 1.2416x over previous
#include <cuda_runtime.h>

#define DIMX   1024
#define NH     16
#define HDIM   64
#define LAT    128
#define QRANK  256
#define BATCH  4
#define SEQ    2048
#define MTOT   (BATCH*SEQ)   // 8192

// ---------------- scratch (device globals: no allocation allowed) -----------
__device__ float g_xtf[(size_t)MTOT * DIMX];         // tf32-rounded x
__device__ float g_cq [(size_t)MTOT * 384];          // [kv_latent | qc] fused
__device__ float g_kv [(size_t)MTOT * 2 * DIMX];     // [K | V] per row
__device__ float g_q  [(size_t)MTOT * DIMX];
__device__ float g_ctx[(size_t)MTOT * DIMX];
__device__ float g_vt [(size_t)BATCH * DIMX * SEQ];  // V^T per batch: [b][d][s]
__device__ float g_wT [1966080];                     // transposed+rounded weights
__device__ float g_bias[384];                        // [b_kvc | b_qc]

// offsets into g_wT (floats); KVC and QC adjacent -> one fused GEMM B operand
#define WT_KVC 0          // [128][1024]
#define WT_QC  131072     // [256][1024]
#define WT_KVU 393216     // [2048][128]
#define WT_QU  655360     // [1024][256]
#define WT_O   917504     // [1024][1024]

// ---------------- helpers ----------------------------------------------------
__device__ __forceinline__ unsigned f2tf(float x){
    unsigned r; asm("cvt.rna.tf32.f32 %0, %1;" : "=r"(r) : "f"(x)); return r;
}
__device__ __forceinline__ float f2tff(float x){ return __uint_as_float(f2tf(x)); }
__device__ __forceinline__ void ldsm4(unsigned* r, unsigned a){
    asm volatile("ldmatrix.sync.aligned.m8n8.x4.shared.b16 {%0,%1,%2,%3}, [%4];"
        : "=r"(r[0]), "=r"(r[1]), "=r"(r[2]), "=r"(r[3]) : "r"(a));
}
__device__ __forceinline__ void mma8(float* c, const unsigned* a, const unsigned* b){
    asm volatile("mma.sync.aligned.m16n8k8.row.col.f32.tf32.tf32.f32 "
        "{%0,%1,%2,%3}, {%4,%5,%6,%7}, {%8,%9}, {%0,%1,%2,%3};"
        : "+f"(c[0]), "+f"(c[1]), "+f"(c[2]), "+f"(c[3])
        : "r"(a[0]), "r"(a[1]), "r"(a[2]), "r"(a[3]), "r"(b[0]), "r"(b[1]));
}
__device__ __forceinline__ void cpa16(unsigned d, const void* s){
    asm volatile("cp.async.cg.shared.global [%0], [%1], 16;" :: "r"(d), "l"(s));
}
__device__ __forceinline__ void cpa_commit(){ asm volatile("cp.async.commit_group;"); }
template<int N> __device__ __forceinline__ void cpa_wait(){
    asm volatile("cp.async.wait_group %0;" :: "n"(N));
}

// swizzled float-index: tile row stride 32 floats (8 chunks of 16B)
#define SWZ32(r,c) (((r)<<5) + ((((c) ^ ((r)&7)) & 7) << 2))
// tile row stride 64 floats (16 chunks)
#define SWZ64(r,c) (((r)<<6) + (((((c)&8) | (((c) ^ (r)) & 7))) << 2))

// ---------------- elementwise tf32 rounding of x -----------------------------
__global__ void cvt_tf32_kernel(const float* __restrict__ in, float* __restrict__ out, int n4)
{
    int i = blockIdx.x*blockDim.x + threadIdx.x;
    for (; i < n4; i += gridDim.x*blockDim.x){
        float4 v = ((const float4*)in)[i];
        ((float4*)out)[i] = make_float4(f2tff(v.x), f2tff(v.y), f2tff(v.z), f2tff(v.w));
    }
}

__global__ void concat_bias_kernel(const float* __restrict__ b1, const float* __restrict__ b2,
                                   float* __restrict__ o)
{
    int t = threadIdx.x;
    o[t] = (t < 128) ? b1[t] : b2[t-128];
}

// ---------------- batched transpose + tf32 round ----------------------------
__global__ void transpose_kernel(const float* __restrict__ in, float* __restrict__ out,
                                 int R, int C, int ics, size_t ibs, size_t obs)
{
    __shared__ float t[32][33];
    const float* ib = in  + blockIdx.z * ibs;
    float*       ob = out + blockIdx.z * obs;
    int r0 = blockIdx.y * 32, c0 = blockIdx.x * 32;
    int tx = threadIdx.x, ty = threadIdx.y;
#pragma unroll
    for (int i = 0; i < 32; i += 8)
        t[ty + i][tx] = ib[(size_t)(r0 + ty + i) * ics + c0 + tx];
    __syncthreads();
#pragma unroll
    for (int i = 0; i < 32; i += 8)
        ob[(size_t)(c0 + ty + i) * R + r0 + tx] = f2tff(t[tx][ty + i]);
}

// ---------------- tf32 mma GEMM, 3-stage cp.async pipeline -------------------
// C[.,N] = A @ Bt^T + bias. A lda-strided, Bt compact [N][K]. Operands already
// tf32-rounded in gmem. BM=BN=128, BK=32, 256 threads, warp tile 64x32.
template<int ROUND>
__global__ __launch_bounds__(256)
void gemm_mma(const float* __restrict__ A, const float* __restrict__ Bt,
              const float* __restrict__ bias, float* __restrict__ C,
              int N, int K, int lda, int ldc)
{
    extern __shared__ float sm[];
    float* As = sm;            // 3 stages x 4096 floats
    float* Bs = sm + 3*4096;
    const int tid  = threadIdx.x;
    const int lane = tid & 31, warp = tid >> 5;
    const int wm = warp >> 2, wn = warp & 3;
    const int m0 = blockIdx.y * 128, n0 = blockIdx.x * 128;
    const unsigned sA = (unsigned)__cvta_generic_to_shared(As);
    const unsigned sB = (unsigned)__cvta_generic_to_shared(Bs);
    const int lrow = tid >> 3, lc4 = tid & 7;
    const int g = lane >> 2, t4 = lane & 3;
    const int ar = lane & 15, asel = lane >> 4;

    auto load_stage = [&](int st, int k0){
#pragma unroll
        for (int i = 0; i < 4; i++){
            int r = lrow + 32*i;
            cpa16(sA + 4*(st*4096 + SWZ32(r, lc4)), A  + (size_t)(m0 + r)*lda + k0 + 4*lc4);
            cpa16(sB + 4*(st*4096 + SWZ32(r, lc4)), Bt + (size_t)(n0 + r)*K   + k0 + 4*lc4);
        }
        cpa_commit();
    };

    const int T = K >> 5;
    load_stage(0, 0);
    if (T > 1) load_stage(1, 32);

    float cacc[4][4][4];
#pragma unroll
    for (int i = 0; i < 4; i++)
#pragma unroll
        for (int j = 0; j < 4; j++)
#pragma unroll
            for (int v = 0; v < 4; v++) cacc[i][j][v] = 0.f;

    for (int it = 0; it < T; it++){
        if (it + 1 < T) cpa_wait<1>(); else cpa_wait<0>();
        __syncthreads();
        if (it + 2 < T) load_stage((it+2)%3, 32*(it+2));
        const int so = (it%3)*4096;
#pragma unroll
        for (int kk = 0; kk < 4; kk++){
            unsigned af[4][4];
#pragma unroll
            for (int mi = 0; mi < 4; mi++)
                ldsm4(af[mi], sA + 4*(so + SWZ32(64*wm + 16*mi + ar, 2*kk + asel)));
            unsigned bt[2][4];
#pragma unroll
            for (int p = 0; p < 2; p++){
                int brow = 32*wn + 8*(2*p + (lane >> 4)) + (lane & 7);
                int bch  = 2*kk + ((lane >> 3) & 1);
                ldsm4(bt[p], sB + 4*(so + SWZ32(brow, bch)));
            }
#pragma unroll
            for (int mi = 0; mi < 4; mi++)
#pragma unroll
                for (int nj = 0; nj < 4; nj++)
                    mma8(cacc[mi][nj], af[mi], &bt[nj >> 1][2*(nj & 1)]);
        }
        __syncthreads();
    }
    // epilogue: += bias; optionally round to tf32 for downstream MMA consumers
#pragma unroll
    for (int mi = 0; mi < 4; mi++){
        int row = m0 + 64*wm + 16*mi + g;
#pragma unroll
        for (int nj = 0; nj < 4; nj++){
            int col = n0 + 32*wn + 8*nj + 2*t4;
            float2 b2 = *(const float2*)(bias + col);
            float v0 = cacc[mi][nj][0] + b2.x, v1 = cacc[mi][nj][1] + b2.y;
            float v2 = cacc[mi][nj][2] + b2.x, v3 = cacc[mi][nj][3] + b2.y;
            if (ROUND){ v0=f2tff(v0); v1=f2tff(v1); v2=f2tff(v2); v3=f2tff(v3); }
            *(float2*)(C + (size_t)row*ldc + col)       = make_float2(v0, v1);
            *(float2*)(C + (size_t)(row + 8)*ldc + col) = make_float2(v2, v3);
        }
    }
}

// ---------------- tf32 mma flash attention (causal, hd=64) ------------------
// 256 threads = 8 warps; warp w owns q rows 16w..16w+15. BM=128, BN=64.
// K/V double-buffered via cp.async; Q smem buffer reused for P.
__global__ __launch_bounds__(256)
void flash_mma(const float* __restrict__ Qm, const float* __restrict__ KVm,
               const float* __restrict__ Vt, float* __restrict__ Om)
{
    extern __shared__ float sm[];
    float* sQP = sm;              // 128*64 = 8192 floats
    float* sK  = sm + 8192;       // 2 stages x 4096
    float* sV  = sm + 16384;      // 2 stages x 4096
    const int tid  = threadIdx.x;
    const int lane = tid & 31, w = tid >> 5;
    const int g = lane >> 2, t4 = lane & 3;
    const int qt = (gridDim.x - 1) - blockIdx.x;   // largest-work blocks first
    const int q0 = qt << 7;
    const int h  = blockIdx.y;
    const int b  = blockIdx.z;

    const unsigned sQPa = (unsigned)__cvta_generic_to_shared(sQP);
    const unsigned sKa  = (unsigned)__cvta_generic_to_shared(sK);
    const unsigned sVa  = (unsigned)__cvta_generic_to_shared(sV);

    const float* Qg = Qm  + ((size_t)(b*SEQ + q0))*DIMX + h*HDIM;
    const float* Kg = KVm + ((size_t)(b*SEQ))*(2*DIMX)  + h*HDIM;
    const float* Vg = Vt  + ((size_t)(b*DIMX + h*HDIM))*SEQ;

    auto load_kv = [&](int st, int k0){
#pragma unroll
        for (int i = 0; i < 4; i++){
            int lin = tid + (i << 8);        // 0..1023
            int r = lin >> 4, c4 = lin & 15;
            cpa16(sKa + 4*(st*4096 + SWZ64(r, c4)), Kg + (size_t)(k0 + r)*(2*DIMX) + (c4 << 2));
            cpa16(sVa + 4*(st*4096 + SWZ64(r, c4)), Vg + (size_t)r*SEQ + k0 + (c4 << 2));
        }
        cpa_commit();
    };

    // Q tile (128 rows x 16 chunks = 2048 chunks, 8/thread); already tf32 in gmem
#pragma unroll
    for (int i = 0; i < 8; i++){
        int lin = tid + (i << 8);
        int r = lin >> 4, c4 = lin & 15;
        cpa16(sQPa + 4*SWZ64(r, c4), Qg + (size_t)r*DIMX + (c4 << 2));
    }
    cpa_commit();
    load_kv(0, 0);

    cpa_wait<1>();       // Q group complete (KV0 may still be in flight)
    __syncthreads();

    // Q fragments -> registers (16 rows x 64 d per warp)
    unsigned qf[8][4];
#pragma unroll
    for (int kk = 0; kk < 8; kk++)
        ldsm4(qf[kk], sQPa + 4*SWZ64(16*w + (lane & 15), 2*kk + (lane >> 4)));

    float m_i[2] = {-1e30f, -1e30f}, l_i[2] = {0.f, 0.f};
    float oacc[8][4];
#pragma unroll
    for (int j = 0; j < 8; j++)
#pragma unroll
        for (int v = 0; v < 4; v++) oacc[j][v] = 0.f;

    const int row0 = q0 + 16*w + g;
    const int nt = 2*qt + 2;
    for (int kt = 0; kt < nt; kt++){
        const int k0 = kt << 6;
        cpa_wait<0>();
        __syncthreads();     // all warps done with previous stage + P/Q buffer
        if (kt + 1 < nt) load_kv((kt+1) & 1, (kt+1) << 6);
        const int so = (kt & 1) * 4096;

        // S = Q K^T : warp tile 16 x 64
        float sacc[8][4];
#pragma unroll
        for (int j = 0; j < 8; j++)
#pragma unroll
            for (int v = 0; v < 4; v++) sacc[j][v] = 0.f;
#pragma unroll
        for (int kk = 0; kk < 8; kk++){
            unsigned bt[4][4];
#pragma unroll
            for (int p = 0; p < 4; p++){
                int brow = 8*(2*p + (lane >> 4)) + (lane & 7);
                int bch  = 2*kk + ((lane >> 3) & 1);
                ldsm4(bt[p], sKa + 4*(so + SWZ64(brow, bch)));
            }
#pragma unroll
            for (int j = 0; j < 8; j++)
                mma8(sacc[j], qf[kk], &bt[j >> 1][2*(j & 1)]);
        }
        // apply 1/sqrt(64) scale (exact power of two; numerics identical to pre-scaled Q)
#pragma unroll
        for (int j = 0; j < 8; j++)
#pragma unroll
            for (int v = 0; v < 4; v++) sacc[j][v] *= 0.125f;

        // causal mask (only tiles crossing this warp's rows)
        if (k0 + 63 > row0){
#pragma unroll
            for (int j = 0; j < 8; j++){
                int c = k0 + 8*j + 2*t4;
                if (c     > row0)     sacc[j][0] = -1e30f;
                if (c + 1 > row0)     sacc[j][1] = -1e30f;
                if (c     > row0 + 8) sacc[j][2] = -1e30f;
                if (c + 1 > row0 + 8) sacc[j][3] = -1e30f;
            }
        }

        // online softmax per row-half (rows row0, row0+8), reduce over 4 lanes
#pragma unroll
        for (int hf = 0; hf < 2; hf++){
            float mx = -1e30f;
#pragma unroll
            for (int j = 0; j < 8; j++)
                mx = fmaxf(mx, fmaxf(sacc[j][2*hf], sacc[j][2*hf + 1]));
            mx = fmaxf(mx, __shfl_xor_sync(0xffffffffu, mx, 1));
            mx = fmaxf(mx, __shfl_xor_sync(0xffffffffu, mx, 2));
            float mn = fmaxf(m_i[hf], mx);
            float al = __expf(m_i[hf] - mn);
            m_i[hf] = mn;
            float rs = 0.f;
#pragma unroll
            for (int j = 0; j < 8; j++){
                sacc[j][2*hf]     = __expf(sacc[j][2*hf]     - mn);
                sacc[j][2*hf + 1] = __expf(sacc[j][2*hf + 1] - mn);
                rs += sacc[j][2*hf] + sacc[j][2*hf + 1];
            }
            rs += __shfl_xor_sync(0xffffffffu, rs, 1);
            rs += __shfl_xor_sync(0xffffffffu, rs, 2);
            l_i[hf] = l_i[hf]*al + rs;
#pragma unroll
            for (int j = 0; j < 8; j++){
                oacc[j][2*hf]     *= al;
                oacc[j][2*hf + 1] *= al;
            }
        }

        // write P (tf32) into sQP rows 16w..16w+15 (per-warp private rows)
#pragma unroll
        for (int j = 0; j < 8; j++){
            int col = 8*j + 2*t4;
            int ch = col >> 2, wi = col & 3;
            uint2 p0 = make_uint2(f2tf(sacc[j][0]), f2tf(sacc[j][1]));
            uint2 p1 = make_uint2(f2tf(sacc[j][2]), f2tf(sacc[j][3]));
            *(uint2*)(sQP + SWZ64(16*w + g,     ch) + wi) = p0;
            *(uint2*)(sQP + SWZ64(16*w + g + 8, ch) + wi) = p1;
        }
        __syncwarp();

        // O += P @ V
#pragma unroll
        for (int kk = 0; kk < 8; kk++){
            unsigned pf[4];
            ldsm4(pf, sQPa + 4*SWZ64(16*w + (lane & 15), 2*kk + (lane >> 4)));
            unsigned bt[4][4];
#pragma unroll
            for (int p = 0; p < 4; p++){
                int brow = 8*(2*p + (lane >> 4)) + (lane & 7);
                int bch  = 2*kk + ((lane >> 3) & 1);
                ldsm4(bt[p], sVa + 4*(so + SWZ64(brow, bch)));
            }
#pragma unroll
            for (int j = 0; j < 8; j++)
                mma8(oacc[j], pf, &bt[j >> 1][2*(j & 1)]);
        }
    }

    // epilogue: normalize, round to tf32 (consumed as MMA A by final GEMM)
    float inv0 = 1.0f / l_i[0], inv1 = 1.0f / l_i[1];
    float* Og = Om + ((size_t)(b*SEQ + q0 + 16*w + g))*DIMX + h*HDIM;
#pragma unroll
    for (int j = 0; j < 8; j++){
        int col = 8*j + 2*t4;
        *(float2*)(Og + col)          = make_float2(f2tff(oacc[j][0]*inv0), f2tff(oacc[j][1]*inv0));
        *(float2*)(Og + 8*DIMX + col) = make_float2(f2tff(oacc[j][2]*inv1), f2tff(oacc[j][3]*inv1));
    }
}

// ---------------- launch -----------------------------------------------------
extern "C" void kernel_launch(void* const* d_in, const int* in_sizes, int n_in,
                              void* d_out, int out_size)
{
    (void)in_sizes; (void)n_in; (void)out_size;
    const float* x     = (const float*)d_in[0];
    // d_in[1] = mask (causal by construction; handled analytically)
    const float* w_kvc = (const float*)d_in[2];
    const float* b_kvc = (const float*)d_in[3];
    const float* w_kvu = (const float*)d_in[4];
    const float* b_kvu = (const float*)d_in[5];
    const float* w_qc  = (const float*)d_in[6];
    const float* b_qc  = (const float*)d_in[7];
    const float* w_qu  = (const float*)d_in[8];
    const float* b_qu  = (const float*)d_in[9];
    const float* w_o   = (const float*)d_in[10];
    const float* b_o   = (const float*)d_in[11];
    float* out = (float*)d_out;

    float *xtf, *cq, *kv, *q, *ctx, *vt, *wT, *bias;
    cudaGetSymbolAddress((void**)&xtf,  g_xtf);
    cudaGetSymbolAddress((void**)&cq,   g_cq);
    cudaGetSymbolAddress((void**)&kv,   g_kv);
    cudaGetSymbolAddress((void**)&q,    g_q);
    cudaGetSymbolAddress((void**)&ctx,  g_ctx);
    cudaGetSymbolAddress((void**)&vt,   g_vt);
    cudaGetSymbolAddress((void**)&wT,   g_wT);
    cudaGetSymbolAddress((void**)&bias, g_bias);

    const int SMEM = 96*1024;
    cudaFuncSetAttribute(gemm_mma<0>, cudaFuncAttributeMaxDynamicSharedMemorySize, SMEM);
    cudaFuncSetAttribute(gemm_mma<1>, cudaFuncAttributeMaxDynamicSharedMemorySize, SMEM);
    cudaFuncSetAttribute(flash_mma,   cudaFuncAttributeMaxDynamicSharedMemorySize, SMEM);

    dim3 tb(32, 8);
    // x -> tf32-rounded copy
    cvt_tf32_kernel<<<2048, 256>>>(x, xtf, MTOT*DIMX/4);
    // transposed + rounded weights [N][K]
    transpose_kernel<<<dim3(128/32, 1024/32), tb>>>(w_kvc, wT + WT_KVC, 1024, 128,  128,  0, 0);
    transpose_kernel<<<dim3(256/32, 1024/32), tb>>>(w_qc,  wT + WT_QC,  1024, 256,  256,  0, 0);
    transpose_kernel<<<dim3(2048/32, 128/32), tb>>>(w_kvu, wT + WT_KVU, 128,  2048, 2048, 0, 0);
    transpose_kernel<<<dim3(1024/32, 256/32), tb>>>(w_qu,  wT + WT_QU,  256,  1024, 1024, 0, 0);
    transpose_kernel<<<dim3(1024/32, 1024/32), tb>>>(w_o,  wT + WT_O,   1024, 1024, 1024, 0, 0);
    concat_bias_kernel<<<1, 384>>>(b_kvc, b_qc, bias);

    // fused [kv_latent | qc] = x @ [w_kvc | w_qc] + [b_kvc | b_qc]   [8192,384]
    gemm_mma<1><<<dim3(3, 64), 256, SMEM>>>(xtf, wT + WT_KVC, bias, cq, 384, DIMX, DIMX, 384);
    // kv = kv_latent @ w_kvu + b_kvu                                  [8192,2048]
    gemm_mma<1><<<dim3(16, 64), 256, SMEM>>>(cq, wT + WT_KVU, b_kvu, kv, 2*DIMX, LAT, 384, 2*DIMX);
    // V^T per batch
    transpose_kernel<<<dim3(1024/32, 2048/32, BATCH), tb>>>(
        kv + DIMX, vt, SEQ, DIMX, 2*DIMX, (size_t)SEQ*2*DIMX, (size_t)DIMX*SEQ);
    // Q = qc @ w_qu + b_qu                                            [8192,1024]
    gemm_mma<1><<<dim3(8, 64), 256, SMEM>>>(cq + 128, wT + WT_QU, b_qu, q, DIMX, QRANK, 384, DIMX);
    // attention
    flash_mma<<<dim3(SEQ/128, NH, BATCH), 256, SMEM>>>(q, kv, vt, ctx);
    // out = ctx @ w_o + b_o (full fp32 epilogue)                      [8192,1024]
    gemm_mma<0><<<dim3(8, 64), 256, SMEM>>>(ctx, wT + WT_O, b_o, out, DIMX, DIMX, DIMX, DIMX);
}